// round 14
// baseline (speedup 1.0000x reference)
#include <cuda_runtime.h>
#include <math.h>

#define TS 16
#define CSTEP 8
#define CSTEP2 4

// Scratch (fp32): feat/outs/gates + hoisted x-part conv results
__device__ float g_scratch[141819904];

__device__ __forceinline__ float sigf(float x) { return 1.f / (1.f + __expf(-x)); }
__device__ __forceinline__ float ftanh(float x) {
    float e = __expf(2.f * x);
    return 1.f - 2.f / (e + 1.f);
}

// ---------------------------------------------------------------------------
// Tile loader: 8 channel planes of 18x19 (halo, zero-pad), strided by 128
// threads with incremental index arithmetic. Single-stream (src only).
// ---------------------------------------------------------------------------
__device__ __forceinline__ void load_tile8(float* __restrict__ dst,
                                           const float* __restrict__ src,
                                           int oy0, int ox0, int H, int W, int HW,
                                           int tid)
{
    int iy = tid / 18, ix = tid % 18;
    int gy = oy0 - 1 + iy, gx = ox0 - 1 + ix;
    int sof = iy * 19 + ix;
    int goff = gy * W + gx;
    for (int i = tid; i < CSTEP * 324; i += 128) {
        float v = 0.f;
        if ((unsigned)gy < (unsigned)H && (unsigned)gx < (unsigned)W)
            v = src[goff];
        dst[sof] = v;
        ix += 2; iy += 7; gy += 7; gx += 2;
        goff += 7 * W + 2; sof += 135;
        if (ix >= 18) { ix -= 18; gx -= 18; iy += 1; gy += 1;
                        goff += W - 18; sof += 1; }
        if (iy >= 18) { iy -= 18; gy -= 18; goff += HW - 18 * W; }
    }
}

// weights loader: 8c x 8co x 9 into flattened [8][8][12]
__device__ __forceinline__ void load_ws8(float* __restrict__ wdst,
                                         const float* __restrict__ Wt,
                                         int co0, int CinTot, int woff, int ci0,
                                         int tid)
{
    for (int i = tid; i < CSTEP * 72; i += 128) {
        int c = i / 72, r = i % 72;
        int co = r / 9, kk = r % 9;
        wdst[c * 96 + co * 12 + kk] =
            Wt[((size_t)(co0 + co) * CinTot + woff + ci0 + c) * 9 + kk];
    }
}

// compute one 8-channel chunk from smem buffers (unchanged math/order)
__device__ __forceinline__ void compute_chunk(const float (* __restrict__ tile)[18][19],
                                              const float (* __restrict__ ws)[8][12],
                                              int tx, int ty,
                                              float acc0[8], float acc1[8])
{
#pragma unroll
    for (int c = 0; c < CSTEP; c++) {
        float a[4][3];
#pragma unroll
        for (int i = 0; i < 4; i++)
#pragma unroll
            for (int j = 0; j < 3; j++)
                a[i][j] = tile[c][2 * ty + i][tx + j];
#pragma unroll
        for (int co = 0; co < 8; co++) {
            float4 wa = *(const float4*)&ws[c][co][0];
            float4 wb = *(const float4*)&ws[c][co][4];
            float w8  = ws[c][co][8];
            acc0[co] += a[0][0]*wa.x + a[0][1]*wa.y + a[0][2]*wa.z
                      + a[1][0]*wa.w + a[1][1]*wb.x + a[1][2]*wb.y
                      + a[2][0]*wb.z + a[2][1]*wb.w + a[2][2]*w8;
            acc1[co] += a[1][0]*wa.x + a[1][1]*wa.y + a[1][2]*wa.z
                      + a[2][0]*wa.w + a[2][1]*wb.x + a[2][2]*wb.y
                      + a[3][0]*wb.z + a[3][1]*wb.w + a[3][2]*w8;
        }
    }
}

// ---------------------------------------------------------------------------
// Batched stride-1 3x3 conv (pad 1), double-buffered smem pipeline.
// grid: (N * Cout/8, H/16, W/16), block (16,8)
// ---------------------------------------------------------------------------
__global__ __launch_bounds__(128)
void conv_pre(const float* __restrict__ in, const float* __restrict__ Wt,
              const float* __restrict__ bias, float* __restrict__ out,
              int Cin, int CinTot, int Cout, int H, int W)
{
    int coutBlocks = Cout >> 3;
    int n   = blockIdx.x / coutBlocks;
    int co0 = (blockIdx.x % coutBlocks) * 8;
    int oy0 = blockIdx.y * TS;
    int ox0 = blockIdx.z * TS;
    int tx = threadIdx.x, ty = threadIdx.y;
    int tid = ty * 16 + tx;

    __shared__ float tile[2][CSTEP][18][19];
    __shared__ __align__(16) float ws[2][CSTEP][8][12];

    int HW = H * W;
    const float* inN = in + (size_t)n * Cin * HW;

    float acc0[8], acc1[8];
#pragma unroll
    for (int i = 0; i < 8; i++) { acc0[i] = 0.f; acc1[i] = 0.f; }

    load_tile8(&tile[0][0][0][0], inN, oy0, ox0, H, W, HW, tid);
    load_ws8(&ws[0][0][0][0], Wt, co0, CinTot, 0, 0, tid);

    int cur = 0;
    for (int ci0 = 0; ci0 < Cin; ci0 += CSTEP) {
        __syncthreads();
        int nxt = ci0 + CSTEP;
        if (nxt < Cin) {
            load_tile8(&tile[cur ^ 1][0][0][0], inN + (size_t)nxt * HW,
                       oy0, ox0, H, W, HW, tid);
            load_ws8(&ws[cur ^ 1][0][0][0], Wt, co0, CinTot, 0, nxt, tid);
        }
        compute_chunk(tile[cur], ws[cur], tx, ty, acc0, acc1);
        cur ^= 1;
    }

    int oy = oy0 + 2 * ty, ox = ox0 + tx;
#pragma unroll
    for (int co = 0; co < 8; co++) {
        float bz = bias[co0 + co];
        size_t o = ((size_t)n * Cout + co0 + co) * HW + (size_t)oy * W + ox;
        out[o]     = acc0[co] + bz;
        out[o + W] = acc1[co] + bz;
    }
}

// ---------------------------------------------------------------------------
// Recurrent h-part conv (t >= 1), double-buffered.
// mode 0 (gates): conv over hprev; r-half output channels (co0 < Ch) store
//   sigf(acc+pre) * hprev  (the r*h product the cand conv needs); z-half
//   stores sigf(acc+pre) unchanged.
// mode 1 (cand): conv over gates r-half (which already holds r*h); epilogue
//   does the GRU update using z (gates z-half) and hprev.
// Seeded by pre (= bias + x-part). grid: (B * Cout/8, H/16, W/16)
// ---------------------------------------------------------------------------
__global__ __launch_bounds__(128)
void gru_conv_h(const float* __restrict__ hprev, const float* __restrict__ Wt,
                const float* __restrict__ pre, const float* __restrict__ gatesIn,
                float* __restrict__ out,
                int Cx, int CinTot, int Ch, int Cout, int H, int W, int mode)
{
    int coutBlocks = Cout >> 3;
    int b   = blockIdx.x / coutBlocks;
    int co0 = (blockIdx.x % coutBlocks) * 8;
    int oy0 = blockIdx.y * TS;
    int ox0 = blockIdx.z * TS;
    int tx = threadIdx.x, ty = threadIdx.y;
    int tid = ty * 16 + tx;

    __shared__ float tile[2][CSTEP][18][19];
    __shared__ __align__(16) float ws[2][CSTEP][8][12];

    int HW = H * W;
    // mode 0: conv input = hprev; mode 1: conv input = gates r-half (= r*h)
    const float* cbase = (mode == 0) ? hprev + (size_t)b * Ch * HW
                                     : gatesIn + (size_t)b * 2 * Ch * HW;

    float acc0[8], acc1[8];
#pragma unroll
    for (int i = 0; i < 8; i++) { acc0[i] = 0.f; acc1[i] = 0.f; }

    load_tile8(&tile[0][0][0][0], cbase, oy0, ox0, H, W, HW, tid);
    load_ws8(&ws[0][0][0][0], Wt, co0, CinTot, Cx, 0, tid);

    int cur = 0;
    for (int ci0 = 0; ci0 < Ch; ci0 += CSTEP) {
        __syncthreads();
        int nxt = ci0 + CSTEP;
        if (nxt < Ch) {
            load_tile8(&tile[cur ^ 1][0][0][0], cbase + (size_t)nxt * HW,
                       oy0, ox0, H, W, HW, tid);
            load_ws8(&ws[cur ^ 1][0][0][0], Wt, co0, CinTot, Cx, nxt, tid);
        }
        compute_chunk(tile[cur], ws[cur], tx, ty, acc0, acc1);
        cur ^= 1;
    }

    int oy = oy0 + 2 * ty, ox = ox0 + tx;
    if (mode == 0) {
        bool rhalf = (co0 < Ch);   // Ch multiple of 8 -> block fully in one half
#pragma unroll
        for (int co = 0; co < 8; co++) {
            int cc = co0 + co;
            size_t po = ((size_t)b * Cout + cc) * HW + (size_t)oy * W + ox;
            float p0 = pre[po], p1 = pre[po + W];
            float s0v = sigf(acc0[co] + p0);
            float s1v = sigf(acc1[co] + p1);
            if (rhalf) {
                size_t ho = (((size_t)b * Ch + cc) * H + oy) * W + ox;
                s0v *= hprev[ho];
                s1v *= hprev[ho + W];
            }
            size_t o = (((size_t)b * Cout + cc) * H + oy) * W + ox;
            out[o]     = s0v;
            out[o + W] = s1v;
        }
    } else {
#pragma unroll
        for (int co = 0; co < 8; co++) {
            int cc = co0 + co;
            size_t po = ((size_t)b * Cout + cc) * HW + (size_t)oy * W + ox;
            float p0 = pre[po], p1 = pre[po + W];
            size_t zo = (((size_t)b * 2 * Ch + Ch + cc) * H + oy) * W + ox;
            float z0 = gatesIn[zo], z1 = gatesIn[zo + W];
            size_t ho = (((size_t)b * Ch + cc) * H + oy) * W + ox;
            float h0v = hprev[ho], h1v = hprev[ho + W];
            out[ho]     = z0 * h0v + (1.f - z0) * ftanh(acc0[co] + p0);
            out[ho + W] = z1 * h1v + (1.f - z1) * ftanh(acc1[co] + p1);
        }
    }
}

// ---------------------------------------------------------------------------
// t = 0 step (h == 0): hn = (1 - sigmoid(z_pre)) * tanh(c_pre), elementwise.
// ---------------------------------------------------------------------------
__global__ void gru_t0(const float* __restrict__ gz, const float* __restrict__ gc,
                       float* __restrict__ hn, int Ch, int HW, int total)
{
    int i = blockIdx.x * 256 + threadIdx.x;
    if (i >= total) return;
    int b = i / (Ch * HW);
    float z = sigf(gz[(size_t)i + (size_t)(b + 1) * Ch * HW]);
    hn[i] = (1.f - z) * ftanh(gc[i]);
}

// ---------------------------------------------------------------------------
// Stride-2 3x3 conv (pad 1) + leaky relu(0.2).
// ---------------------------------------------------------------------------
__global__ void conv_s2_lrelu(const float* __restrict__ in, const float* __restrict__ Wt,
                              const float* __restrict__ bias, float* __restrict__ out,
                              int Cin, int Cout, int Hin, int Win, int sOuter, int sInner)
{
    int coutBlocks = Cout >> 3;
    int n  = blockIdx.x / coutBlocks;
    int cb = blockIdx.x % coutBlocks;
    int co0 = cb * 8;
    int t = n / 8, b = n % 8;
    const float* inN = in + (size_t)t * sOuter + (size_t)b * sInner;
    int Hout = Hin >> 1, Wout = Win >> 1;
    int oy0 = blockIdx.y * TS, ox0 = blockIdx.z * TS;
    int tx = threadIdx.x, ty = threadIdx.y;
    int tid = ty * 16 + tx;

    __shared__ float tile[CSTEP2][33][35];
    __shared__ float ws[CSTEP2][8][9];

    float acc0[8], acc1[8];
#pragma unroll
    for (int i = 0; i < 8; i++) { acc0[i] = 0.f; acc1[i] = 0.f; }

    for (int ci0 = 0; ci0 < Cin; ci0 += CSTEP2) {
        __syncthreads();
        for (int i = tid; i < CSTEP2 * 1089; i += 128) {
            int c = i / 1089, p = i % 1089;
            int ly = p / 33, lx = p % 33;
            int gy = 2 * oy0 - 1 + ly, gx = 2 * ox0 - 1 + lx;
            float v = 0.f;
            int ci = ci0 + c;
            if (ci < Cin && gy >= 0 && gy < Hin && gx >= 0 && gx < Win)
                v = inN[((size_t)ci * Hin + gy) * Win + gx];
            tile[c][ly][lx] = v;
        }
        for (int i = tid; i < CSTEP2 * 72; i += 128) {
            int c = i / 72, r = i % 72;
            int co = r / 9, k = r % 9;
            float wv = 0.f;
            if (ci0 + c < Cin)
                wv = Wt[((size_t)(co0 + co) * Cin + (ci0 + c)) * 9 + k];
            ws[c][co][k] = wv;
        }
        __syncthreads();

#pragma unroll
        for (int c = 0; c < CSTEP2; c++) {
            float a[5][3];
#pragma unroll
            for (int i = 0; i < 5; i++)
#pragma unroll
                for (int j = 0; j < 3; j++)
                    a[i][j] = tile[c][4 * ty + i][2 * tx + j];
#pragma unroll
            for (int co = 0; co < 8; co++) {
                float w0 = ws[c][co][0], w1 = ws[c][co][1], w2 = ws[c][co][2];
                float w3 = ws[c][co][3], w4 = ws[c][co][4], w5 = ws[c][co][5];
                float w6 = ws[c][co][6], w7 = ws[c][co][7], w8 = ws[c][co][8];
                acc0[co] += a[0][0]*w0 + a[0][1]*w1 + a[0][2]*w2
                          + a[1][0]*w3 + a[1][1]*w4 + a[1][2]*w5
                          + a[2][0]*w6 + a[2][1]*w7 + a[2][2]*w8;
                acc1[co] += a[2][0]*w0 + a[2][1]*w1 + a[2][2]*w2
                          + a[3][0]*w3 + a[3][1]*w4 + a[3][2]*w5
                          + a[4][0]*w6 + a[4][1]*w7 + a[4][2]*w8;
            }
        }
    }

    int oy = oy0 + 2 * ty, ox = ox0 + tx;
#pragma unroll
    for (int co = 0; co < 8; co++) {
        float bz = bias[co0 + co];
        float v0 = acc0[co] + bz, v1 = acc1[co] + bz;
        v0 = v0 > 0.f ? v0 : 0.2f * v0;
        v1 = v1 > 0.f ? v1 : 0.2f * v1;
        size_t o = (((size_t)n * Cout + co0 + co) * Hout + oy) * Wout + ox;
        out[o]        = v0;
        out[o + Wout] = v1;
    }
}

// ---------------- streams/events (created once at load time) ----------------
static cudaStream_t g_sB, g_sC, g_sD, g_sE;
static cudaEvent_t g_ev1[10], g_evB[10], g_ev2[10], g_evD[10], g_evE;
static bool g_streams_ok = [] {
    if (cudaStreamCreateWithFlags(&g_sB, cudaStreamNonBlocking) != cudaSuccess) return false;
    if (cudaStreamCreateWithFlags(&g_sC, cudaStreamNonBlocking) != cudaSuccess) return false;
    if (cudaStreamCreateWithFlags(&g_sD, cudaStreamNonBlocking) != cudaSuccess) return false;
    if (cudaStreamCreateWithFlags(&g_sE, cudaStreamNonBlocking) != cudaSuccess) return false;
    for (int i = 0; i < 10; i++) {
        cudaEventCreateWithFlags(&g_ev1[i], cudaEventDisableTiming);
        cudaEventCreateWithFlags(&g_evB[i], cudaEventDisableTiming);
        cudaEventCreateWithFlags(&g_ev2[i], cudaEventDisableTiming);
        cudaEventCreateWithFlags(&g_evD[i], cudaEventDisableTiming);
    }
    cudaEventCreateWithFlags(&g_evE, cudaEventDisableTiming);
    return true;
}();

extern "C" void kernel_launch(void* const* d_in, const int* in_sizes, int n_in,
                              void* d_out, int out_size)
{
    const float* x   = (const float*)d_in[0];
    const float* W1  = (const float*)d_in[1];
    const float* b1  = (const float*)d_in[2];
    const float* Wg1 = (const float*)d_in[3];
    const float* bg1 = (const float*)d_in[4];
    const float* Wc1 = (const float*)d_in[5];
    const float* bc1 = (const float*)d_in[6];
    const float* W2  = (const float*)d_in[7];
    const float* b2  = (const float*)d_in[8];
    const float* Wg2 = (const float*)d_in[9];
    const float* bg2 = (const float*)d_in[10];
    const float* Wc2 = (const float*)d_in[11];
    const float* bc2 = (const float*)d_in[12];
    const float* W3  = (const float*)d_in[13];
    const float* b3  = (const float*)d_in[14];
    const float* Wg3 = (const float*)d_in[15];
    const float* bg3 = (const float*)d_in[16];
    const float* Wc3 = (const float*)d_in[17];
    const float* bc3 = (const float*)d_in[18];

    float* base = nullptr;
    cudaGetSymbolAddress((void**)&base, g_scratch);

    float* feat1  = base;                   // 5,242,880
    float* outs1  = base + 5242880;         // 20,971,520
    float* feat2  = base + 26214400;        // 5,242,880
    float* outs2  = base + 31457280;        // 7,864,320
    float* feat3  = base + 39321600;        // 1,966,080
    float* outs3  = base + 41287680;        // 1,966,080
    float* gates1 = base + 43253760;        // 4,194,304 (8*128*4096)
    float* gxg1   = base + 47448064;        // 41,943,040
    float* gxc1   = base + 89391104;        // 20,971,520
    float* gxg2   = base + 110362624;       // 15,728,640
    float* gxc2   = base + 126091264;       // 7,864,320
    float* gxg3   = base + 133955584;       // 3,932,160
    float* gxc3   = base + 137887744;       // 1,966,080
    float* gates2 = base + 139853824;       // 1,572,864 (8*192*1024)
    float* gates3 = base + 141426688;       // 393,216   (8*192*256)

    dim3 blk(16, 8);
    cudaStream_t s0 = 0;

    const size_t O1T = 8UL * 64 * 4096;
    const size_t F2T = 8UL * 64 * 1024;
    const size_t GG2 = 8UL * 192 * 1024;
    const size_t GC2 = 8UL * 96 * 1024;
    const size_t O2T = 8UL * 96 * 1024;
    const size_t F3T = 8UL * 96 * 256;
    const size_t GG3 = 8UL * 192 * 256;
    const size_t GC3 = 8UL * 96 * 256;
    const size_t O3T = 8UL * 96 * 256;

    // ================= Stage 1 on s0 (saturating) =================
    conv_s2_lrelu<<<dim3(80 * 2, 4, 4), blk, 0, s0>>>(x, W1, b1, feat1,
                                                      1, 16, 128, 128, 16384, 163840);
    conv_pre<<<dim3(80 * 16, 4, 4), blk, 0, s0>>>(feat1, Wg1, bg1, gxg1, 16, 80, 128, 64, 64);
    conv_pre<<<dim3(80 * 8, 4, 4), blk, 0, s0>>>(feat1, Wc1, bc1, gxc1, 16, 80, 64, 64, 64);
    gru_t0<<<(8 * 64 * 4096 + 255) / 256, 256, 0, s0>>>(gxg1, gxc1, outs1, 64, 4096,
                                                        8 * 64 * 4096);
    cudaEventRecord(g_ev1[0], s0);
    for (int t = 1; t < 10; t++) {
        const float* hp = outs1 + (size_t)(t - 1) * O1T;
        float* hn = outs1 + (size_t)t * O1T;
        gru_conv_h<<<dim3(8 * 16, 4, 4), blk, 0, s0>>>(hp, Wg1, gxg1 + (size_t)t * 8 * 128 * 4096,
                                                       gates1, gates1, 16, 80, 64, 128, 64, 64, 0);
        gru_conv_h<<<dim3(8 * 8, 4, 4), blk, 0, s0>>>(hp, Wc1, gxc1 + (size_t)t * O1T,
                                                      gates1, hn, 16, 80, 64, 64, 64, 64, 1);
        cudaEventRecord(g_ev1[t], s0);
    }

    // ================= Stage 2 pre (stream B) =================
    for (int t = 0; t < 10; t++) {
        cudaStreamWaitEvent(g_sB, g_ev1[t], 0);
        conv_s2_lrelu<<<dim3(8 * 8, 2, 2), blk, 0, g_sB>>>(outs1 + (size_t)t * O1T, W2, b2,
                                                           feat2 + (size_t)t * F2T,
                                                           64, 64, 64, 64, 0, 64 * 4096);
        conv_pre<<<dim3(8 * 24, 2, 2), blk, 0, g_sB>>>(feat2 + (size_t)t * F2T, Wg2, bg2,
                                                       gxg2 + (size_t)t * GG2,
                                                       64, 160, 192, 32, 32);
        conv_pre<<<dim3(8 * 12, 2, 2), blk, 0, g_sB>>>(feat2 + (size_t)t * F2T, Wc2, bc2,
                                                       gxc2 + (size_t)t * GC2,
                                                       64, 160, 96, 32, 32);
        cudaEventRecord(g_evB[t], g_sB);
    }

    // ================= Stage 2 recurrence (stream C) =================
    cudaStreamWaitEvent(g_sC, g_evB[0], 0);
    gru_t0<<<(int)((O2T + 255) / 256), 256, 0, g_sC>>>(gxg2, gxc2, outs2, 96, 1024, (int)O2T);
    cudaEventRecord(g_ev2[0], g_sC);
    for (int t = 1; t < 10; t++) {
        cudaStreamWaitEvent(g_sC, g_evB[t], 0);
        const float* hp = outs2 + (size_t)(t - 1) * O2T;
        float* hn = outs2 + (size_t)t * O2T;
        gru_conv_h<<<dim3(8 * 24, 2, 2), blk, 0, g_sC>>>(hp, Wg2, gxg2 + (size_t)t * GG2,
                                                         gates2, gates2, 64, 160, 96, 192, 32, 32, 0);
        gru_conv_h<<<dim3(8 * 12, 2, 2), blk, 0, g_sC>>>(hp, Wc2, gxc2 + (size_t)t * GC2,
                                                         gates2, hn, 64, 160, 96, 96, 32, 32, 1);
        cudaEventRecord(g_ev2[t], g_sC);
    }

    // ================= Stage 3 pre (stream D) =================
    for (int t = 0; t < 10; t++) {
        cudaStreamWaitEvent(g_sD, g_ev2[t], 0);
        conv_s2_lrelu<<<dim3(8 * 12, 1, 1), blk, 0, g_sD>>>(outs2 + (size_t)t * O2T, W3, b3,
                                                            feat3 + (size_t)t * F3T,
                                                            96, 96, 32, 32, 0, 96 * 1024);
        conv_pre<<<dim3(8 * 24, 1, 1), blk, 0, g_sD>>>(feat3 + (size_t)t * F3T, Wg3, bg3,
                                                       gxg3 + (size_t)t * GG3,
                                                       96, 192, 192, 16, 16);
        conv_pre<<<dim3(8 * 12, 1, 1), blk, 0, g_sD>>>(feat3 + (size_t)t * F3T, Wc3, bc3,
                                                       gxc3 + (size_t)t * GC3,
                                                       96, 192, 96, 16, 16);
        cudaEventRecord(g_evD[t], g_sD);
    }

    // ================= Stage 3 recurrence (stream E) =================
    cudaStreamWaitEvent(g_sE, g_evD[0], 0);
    gru_t0<<<(int)((O3T + 255) / 256), 256, 0, g_sE>>>(gxg3, gxc3, outs3, 96, 256, (int)O3T);
    for (int t = 1; t < 10; t++) {
        cudaStreamWaitEvent(g_sE, g_evD[t], 0);
        const float* hp = outs3 + (size_t)(t - 1) * O3T;
        float* hn = outs3 + (size_t)t * O3T;
        gru_conv_h<<<dim3(8 * 24, 1, 1), blk, 0, g_sE>>>(hp, Wg3, gxg3 + (size_t)t * GG3,
                                                         gates3, gates3, 96, 192, 96, 192, 16, 16, 0);
        gru_conv_h<<<dim3(8 * 12, 1, 1), blk, 0, g_sE>>>(hp, Wc3, gxc3 + (size_t)t * GC3,
                                                         gates3, hn, 96, 192, 96, 96, 16, 16, 1);
    }
    cudaEventRecord(g_evE, g_sE);

    // ---------------- Join all forked streams back into s0 ----------------
    cudaStreamWaitEvent(s0, g_evB[9], 0);
    cudaStreamWaitEvent(s0, g_ev2[9], 0);
    cudaStreamWaitEvent(s0, g_evD[9], 0);
    cudaStreamWaitEvent(s0, g_evE, 0);

    // ---------------- Assemble output: (h1, h2, h3) flattened ----------------
    float* out = (float*)d_out;
    cudaMemcpyAsync(out, outs1 + 9UL * O1T,
                    O1T * sizeof(float), cudaMemcpyDeviceToDevice, s0);
    cudaMemcpyAsync(out + 2097152, outs2 + 9UL * O2T,
                    O2T * sizeof(float), cudaMemcpyDeviceToDevice, s0);
    cudaMemcpyAsync(out + 2097152 + 786432, outs3 + 9UL * O3T,
                    O3T * sizeof(float), cudaMemcpyDeviceToDevice, s0);
}

// round 16
// speedup vs baseline: 1.0038x; 1.0038x over previous
#include <cuda_runtime.h>
#include <math.h>

#define TS 16
#define CSTEP 8
#define CSTEP2 4

// Scratch (fp32): feat/outs/gates + hoisted x-part conv results
__device__ float g_scratch[141819904];

__device__ __forceinline__ float sigf(float x) { return 1.f / (1.f + __expf(-x)); }
__device__ __forceinline__ float ftanh(float x) {
    float e = __expf(2.f * x);
    return 1.f - 2.f / (e + 1.f);
}

// ---------------------------------------------------------------------------
// Tile loader: 8 channel planes of 18x19 (halo, zero-pad), strided by 128
// threads with incremental index arithmetic. withR: multiply by r-gate plane.
// ---------------------------------------------------------------------------
__device__ __forceinline__ void load_tile8(float* __restrict__ dst,
                                           const float* __restrict__ src,
                                           const float* __restrict__ rs,
                                           int oy0, int ox0, int H, int W, int HW,
                                           int tid, bool withR)
{
    int iy = tid / 18, ix = tid % 18;
    int gy = oy0 - 1 + iy, gx = ox0 - 1 + ix;
    int sof = iy * 19 + ix;
    int goff = gy * W + gx;
    if (withR) {
        for (int i = tid; i < CSTEP * 324; i += 128) {
            float v = 0.f;
            if ((unsigned)gy < (unsigned)H && (unsigned)gx < (unsigned)W)
                v = src[goff] * rs[goff];
            dst[sof] = v;
            ix += 2; iy += 7; gy += 7; gx += 2;
            goff += 7 * W + 2; sof += 135;
            if (ix >= 18) { ix -= 18; gx -= 18; iy += 1; gy += 1;
                            goff += W - 18; sof += 1; }
            if (iy >= 18) { iy -= 18; gy -= 18; goff += HW - 18 * W; }
        }
    } else {
        for (int i = tid; i < CSTEP * 324; i += 128) {
            float v = 0.f;
            if ((unsigned)gy < (unsigned)H && (unsigned)gx < (unsigned)W)
                v = src[goff];
            dst[sof] = v;
            ix += 2; iy += 7; gy += 7; gx += 2;
            goff += 7 * W + 2; sof += 135;
            if (ix >= 18) { ix -= 18; gx -= 18; iy += 1; gy += 1;
                            goff += W - 18; sof += 1; }
            if (iy >= 18) { iy -= 18; gy -= 18; goff += HW - 18 * W; }
        }
    }
}

// weights loader: 8c x 8co x 9 into flattened [8][8][12]
__device__ __forceinline__ void load_ws8(float* __restrict__ wdst,
                                         const float* __restrict__ Wt,
                                         int co0, int CinTot, int woff, int ci0,
                                         int tid)
{
    for (int i = tid; i < CSTEP * 72; i += 128) {
        int c = i / 72, r = i % 72;
        int co = r / 9, kk = r % 9;
        wdst[c * 96 + co * 12 + kk] =
            Wt[((size_t)(co0 + co) * CinTot + woff + ci0 + c) * 9 + kk];
    }
}

// compute one 8-channel chunk from smem buffers (unchanged math/order)
__device__ __forceinline__ void compute_chunk(const float (* __restrict__ tile)[18][19],
                                              const float (* __restrict__ ws)[8][12],
                                              int tx, int ty,
                                              float acc0[8], float acc1[8])
{
#pragma unroll
    for (int c = 0; c < CSTEP; c++) {
        float a[4][3];
#pragma unroll
        for (int i = 0; i < 4; i++)
#pragma unroll
            for (int j = 0; j < 3; j++)
                a[i][j] = tile[c][2 * ty + i][tx + j];
#pragma unroll
        for (int co = 0; co < 8; co++) {
            float4 wa = *(const float4*)&ws[c][co][0];
            float4 wb = *(const float4*)&ws[c][co][4];
            float w8  = ws[c][co][8];
            acc0[co] += a[0][0]*wa.x + a[0][1]*wa.y + a[0][2]*wa.z
                      + a[1][0]*wa.w + a[1][1]*wb.x + a[1][2]*wb.y
                      + a[2][0]*wb.z + a[2][1]*wb.w + a[2][2]*w8;
            acc1[co] += a[1][0]*wa.x + a[1][1]*wa.y + a[1][2]*wa.z
                      + a[2][0]*wa.w + a[2][1]*wb.x + a[2][2]*wb.y
                      + a[3][0]*wb.z + a[3][1]*wb.w + a[3][2]*w8;
        }
    }
}

// ---------------------------------------------------------------------------
// Batched stride-1 3x3 conv (pad 1), double-buffered smem pipeline.
// grid: (N * Cout/8, H/16, W/16), block (16,8)
// ---------------------------------------------------------------------------
__global__ __launch_bounds__(128)
void conv_pre(const float* __restrict__ in, const float* __restrict__ Wt,
              const float* __restrict__ bias, float* __restrict__ out,
              int Cin, int CinTot, int Cout, int H, int W)
{
    int coutBlocks = Cout >> 3;
    int n   = blockIdx.x / coutBlocks;
    int co0 = (blockIdx.x % coutBlocks) * 8;
    int oy0 = blockIdx.y * TS;
    int ox0 = blockIdx.z * TS;
    int tx = threadIdx.x, ty = threadIdx.y;
    int tid = ty * 16 + tx;

    __shared__ float tile[2][CSTEP][18][19];
    __shared__ __align__(16) float ws[2][CSTEP][8][12];

    int HW = H * W;
    const float* inN = in + (size_t)n * Cin * HW;

    float acc0[8], acc1[8];
#pragma unroll
    for (int i = 0; i < 8; i++) { acc0[i] = 0.f; acc1[i] = 0.f; }

    load_tile8(&tile[0][0][0][0], inN, nullptr, oy0, ox0, H, W, HW, tid, false);
    load_ws8(&ws[0][0][0][0], Wt, co0, CinTot, 0, 0, tid);

    int cur = 0;
    for (int ci0 = 0; ci0 < Cin; ci0 += CSTEP) {
        __syncthreads();
        int nxt = ci0 + CSTEP;
        if (nxt < Cin) {
            load_tile8(&tile[cur ^ 1][0][0][0], inN + (size_t)nxt * HW, nullptr,
                       oy0, ox0, H, W, HW, tid, false);
            load_ws8(&ws[cur ^ 1][0][0][0], Wt, co0, CinTot, 0, nxt, tid);
        }
        compute_chunk(tile[cur], ws[cur], tx, ty, acc0, acc1);
        cur ^= 1;
    }

    int oy = oy0 + 2 * ty, ox = ox0 + tx;
#pragma unroll
    for (int co = 0; co < 8; co++) {
        float bz = bias[co0 + co];
        size_t o = ((size_t)n * Cout + co0 + co) * HW + (size_t)oy * W + ox;
        out[o]     = acc0[co] + bz;
        out[o + W] = acc1[co] + bz;
    }
}

// ---------------------------------------------------------------------------
// Recurrent h-part conv (t >= 1), double-buffered. mode 0: gates -> sigmoid.
// mode 1: cand (r*h in loader) -> GRU update. Seeded by pre (= bias + x-part).
// Launched per-batch: pointers pre-offset, grid b-dim = 1 (b = 0 inside).
// grid: (Cout/8, H/16, W/16)
// ---------------------------------------------------------------------------
__global__ __launch_bounds__(128)
void gru_conv_h(const float* __restrict__ hprev, const float* __restrict__ Wt,
                const float* __restrict__ pre, const float* __restrict__ gatesIn,
                float* __restrict__ out,
                int Cx, int CinTot, int Ch, int Cout, int H, int W, int mode)
{
    int coutBlocks = Cout >> 3;
    int b   = blockIdx.x / coutBlocks;
    int co0 = (blockIdx.x % coutBlocks) * 8;
    int oy0 = blockIdx.y * TS;
    int ox0 = blockIdx.z * TS;
    int tx = threadIdx.x, ty = threadIdx.y;
    int tid = ty * 16 + tx;

    __shared__ float tile[2][CSTEP][18][19];
    __shared__ __align__(16) float ws[2][CSTEP][8][12];

    int HW = H * W;
    const float* hbase = hprev + (size_t)b * Ch * HW;
    const float* rbase = gatesIn + (size_t)b * 2 * Ch * HW;
    bool withR = (mode != 0);

    float acc0[8], acc1[8];
#pragma unroll
    for (int i = 0; i < 8; i++) { acc0[i] = 0.f; acc1[i] = 0.f; }

    load_tile8(&tile[0][0][0][0], hbase, rbase, oy0, ox0, H, W, HW, tid, withR);
    load_ws8(&ws[0][0][0][0], Wt, co0, CinTot, Cx, 0, tid);

    int cur = 0;
    for (int ci0 = 0; ci0 < Ch; ci0 += CSTEP) {
        __syncthreads();
        int nxt = ci0 + CSTEP;
        if (nxt < Ch) {
            load_tile8(&tile[cur ^ 1][0][0][0], hbase + (size_t)nxt * HW,
                       rbase + (size_t)nxt * HW, oy0, ox0, H, W, HW, tid, withR);
            load_ws8(&ws[cur ^ 1][0][0][0], Wt, co0, CinTot, Cx, nxt, tid);
        }
        compute_chunk(tile[cur], ws[cur], tx, ty, acc0, acc1);
        cur ^= 1;
    }

    int oy = oy0 + 2 * ty, ox = ox0 + tx;
    if (mode == 0) {
#pragma unroll
        for (int co = 0; co < 8; co++) {
            size_t po = ((size_t)b * Cout + co0 + co) * HW + (size_t)oy * W + ox;
            float p0 = pre[po], p1 = pre[po + W];
            size_t o = (((size_t)b * Cout + co0 + co) * H + oy) * W + ox;
            out[o]     = sigf(acc0[co] + p0);
            out[o + W] = sigf(acc1[co] + p1);
        }
    } else {
#pragma unroll
        for (int co = 0; co < 8; co++) {
            int cc = co0 + co;
            size_t po = ((size_t)b * Cout + cc) * HW + (size_t)oy * W + ox;
            float p0 = pre[po], p1 = pre[po + W];
            size_t zo = (((size_t)b * 2 * Ch + Ch + cc) * H + oy) * W + ox;
            float z0 = gatesIn[zo], z1 = gatesIn[zo + W];
            size_t ho = (((size_t)b * Ch + cc) * H + oy) * W + ox;
            float h0v = hprev[ho], h1v = hprev[ho + W];
            out[ho]     = z0 * h0v + (1.f - z0) * ftanh(acc0[co] + p0);
            out[ho + W] = z1 * h1v + (1.f - z1) * ftanh(acc1[co] + p1);
        }
    }
}

// ---------------------------------------------------------------------------
// t = 0 step (h == 0): hn = (1 - sigmoid(z_pre)) * tanh(c_pre), elementwise.
// ---------------------------------------------------------------------------
__global__ void gru_t0(const float* __restrict__ gz, const float* __restrict__ gc,
                       float* __restrict__ hn, int Ch, int HW, int total)
{
    int i = blockIdx.x * 256 + threadIdx.x;
    if (i >= total) return;
    int b = i / (Ch * HW);
    float z = sigf(gz[(size_t)i + (size_t)(b + 1) * Ch * HW]);
    hn[i] = (1.f - z) * ftanh(gc[i]);
}

// ---------------------------------------------------------------------------
// Stride-2 3x3 conv (pad 1) + leaky relu(0.2).
// ---------------------------------------------------------------------------
__global__ void conv_s2_lrelu(const float* __restrict__ in, const float* __restrict__ Wt,
                              const float* __restrict__ bias, float* __restrict__ out,
                              int Cin, int Cout, int Hin, int Win, int sOuter, int sInner)
{
    int coutBlocks = Cout >> 3;
    int n  = blockIdx.x / coutBlocks;
    int cb = blockIdx.x % coutBlocks;
    int co0 = cb * 8;
    int t = n / 8, b = n % 8;
    const float* inN = in + (size_t)t * sOuter + (size_t)b * sInner;
    int Hout = Hin >> 1, Wout = Win >> 1;
    int oy0 = blockIdx.y * TS, ox0 = blockIdx.z * TS;
    int tx = threadIdx.x, ty = threadIdx.y;
    int tid = ty * 16 + tx;

    __shared__ float tile[CSTEP2][33][35];
    __shared__ float ws[CSTEP2][8][9];

    float acc0[8], acc1[8];
#pragma unroll
    for (int i = 0; i < 8; i++) { acc0[i] = 0.f; acc1[i] = 0.f; }

    for (int ci0 = 0; ci0 < Cin; ci0 += CSTEP2) {
        __syncthreads();
        for (int i = tid; i < CSTEP2 * 1089; i += 128) {
            int c = i / 1089, p = i % 1089;
            int ly = p / 33, lx = p % 33;
            int gy = 2 * oy0 - 1 + ly, gx = 2 * ox0 - 1 + lx;
            float v = 0.f;
            int ci = ci0 + c;
            if (ci < Cin && gy >= 0 && gy < Hin && gx >= 0 && gx < Win)
                v = inN[((size_t)ci * Hin + gy) * Win + gx];
            tile[c][ly][lx] = v;
        }
        for (int i = tid; i < CSTEP2 * 72; i += 128) {
            int c = i / 72, r = i % 72;
            int co = r / 9, k = r % 9;
            float wv = 0.f;
            if (ci0 + c < Cin)
                wv = Wt[((size_t)(co0 + co) * Cin + (ci0 + c)) * 9 + k];
            ws[c][co][k] = wv;
        }
        __syncthreads();

#pragma unroll
        for (int c = 0; c < CSTEP2; c++) {
            float a[5][3];
#pragma unroll
            for (int i = 0; i < 5; i++)
#pragma unroll
                for (int j = 0; j < 3; j++)
                    a[i][j] = tile[c][4 * ty + i][2 * tx + j];
#pragma unroll
            for (int co = 0; co < 8; co++) {
                float w0 = ws[c][co][0], w1 = ws[c][co][1], w2 = ws[c][co][2];
                float w3 = ws[c][co][3], w4 = ws[c][co][4], w5 = ws[c][co][5];
                float w6 = ws[c][co][6], w7 = ws[c][co][7], w8 = ws[c][co][8];
                acc0[co] += a[0][0]*w0 + a[0][1]*w1 + a[0][2]*w2
                          + a[1][0]*w3 + a[1][1]*w4 + a[1][2]*w5
                          + a[2][0]*w6 + a[2][1]*w7 + a[2][2]*w8;
                acc1[co] += a[2][0]*w0 + a[2][1]*w1 + a[2][2]*w2
                          + a[3][0]*w3 + a[3][1]*w4 + a[3][2]*w5
                          + a[4][0]*w6 + a[4][1]*w7 + a[4][2]*w8;
            }
        }
    }

    int oy = oy0 + 2 * ty, ox = ox0 + tx;
#pragma unroll
    for (int co = 0; co < 8; co++) {
        float bz = bias[co0 + co];
        float v0 = acc0[co] + bz, v1 = acc1[co] + bz;
        v0 = v0 > 0.f ? v0 : 0.2f * v0;
        v1 = v1 > 0.f ? v1 : 0.2f * v1;
        size_t o = (((size_t)n * Cout + co0 + co) * Hout + oy) * Wout + ox;
        out[o]        = v0;
        out[o + Wout] = v1;
    }
}

// ---------------- streams/events (created once at load time) ----------------
static cudaStream_t g_sB, g_sC, g_sD, g_sE, g_s1[8];
static cudaEvent_t g_evT0, g_e1[8][10], g_evB[10], g_ev2[10], g_evD[10], g_evE;
static bool g_streams_ok = [] {
    cudaStreamCreateWithFlags(&g_sB, cudaStreamNonBlocking);
    cudaStreamCreateWithFlags(&g_sC, cudaStreamNonBlocking);
    cudaStreamCreateWithFlags(&g_sD, cudaStreamNonBlocking);
    cudaStreamCreateWithFlags(&g_sE, cudaStreamNonBlocking);
    for (int b = 0; b < 8; b++) {
        cudaStreamCreateWithFlags(&g_s1[b], cudaStreamNonBlocking);
        for (int t = 0; t < 10; t++)
            cudaEventCreateWithFlags(&g_e1[b][t], cudaEventDisableTiming);
    }
    cudaEventCreateWithFlags(&g_evT0, cudaEventDisableTiming);
    for (int i = 0; i < 10; i++) {
        cudaEventCreateWithFlags(&g_evB[i], cudaEventDisableTiming);
        cudaEventCreateWithFlags(&g_ev2[i], cudaEventDisableTiming);
        cudaEventCreateWithFlags(&g_evD[i], cudaEventDisableTiming);
    }
    cudaEventCreateWithFlags(&g_evE, cudaEventDisableTiming);
    return true;
}();

extern "C" void kernel_launch(void* const* d_in, const int* in_sizes, int n_in,
                              void* d_out, int out_size)
{
    const float* x   = (const float*)d_in[0];
    const float* W1  = (const float*)d_in[1];
    const float* b1  = (const float*)d_in[2];
    const float* Wg1 = (const float*)d_in[3];
    const float* bg1 = (const float*)d_in[4];
    const float* Wc1 = (const float*)d_in[5];
    const float* bc1 = (const float*)d_in[6];
    const float* W2  = (const float*)d_in[7];
    const float* b2  = (const float*)d_in[8];
    const float* Wg2 = (const float*)d_in[9];
    const float* bg2 = (const float*)d_in[10];
    const float* Wc2 = (const float*)d_in[11];
    const float* bc2 = (const float*)d_in[12];
    const float* W3  = (const float*)d_in[13];
    const float* b3  = (const float*)d_in[14];
    const float* Wg3 = (const float*)d_in[15];
    const float* bg3 = (const float*)d_in[16];
    const float* Wc3 = (const float*)d_in[17];
    const float* bc3 = (const float*)d_in[18];

    float* base = nullptr;
    cudaGetSymbolAddress((void**)&base, g_scratch);

    float* feat1  = base;                   // 5,242,880
    float* outs1  = base + 5242880;         // 20,971,520
    float* feat2  = base + 26214400;        // 5,242,880
    float* outs2  = base + 31457280;        // 7,864,320
    float* feat3  = base + 39321600;        // 1,966,080
    float* outs3  = base + 41287680;        // 1,966,080
    float* gates1 = base + 43253760;        // 4,194,304 (8*128*4096)
    float* gxg1   = base + 47448064;        // 41,943,040
    float* gxc1   = base + 89391104;        // 20,971,520
    float* gxg2   = base + 110362624;       // 15,728,640
    float* gxc2   = base + 126091264;       // 7,864,320
    float* gxg3   = base + 133955584;       // 3,932,160
    float* gxc3   = base + 137887744;       // 1,966,080
    float* gates2 = base + 139853824;       // 1,572,864 (8*192*1024)
    float* gates3 = base + 141426688;       // 393,216   (8*192*256)

    dim3 blk(16, 8);
    cudaStream_t s0 = 0;

    const size_t O1T = 8UL * 64 * 4096;   // outs1 per t
    const size_t H1B = 64UL * 4096;       // outs1 per batch
    const size_t G1B = 128UL * 4096;      // gates1/gxg1 per batch
    const size_t F2T = 8UL * 64 * 1024;
    const size_t GG2 = 8UL * 192 * 1024;
    const size_t GC2 = 8UL * 96 * 1024;
    const size_t O2T = 8UL * 96 * 1024;
    const size_t F3T = 8UL * 96 * 256;
    const size_t GG3 = 8UL * 192 * 256;
    const size_t GC3 = 8UL * 96 * 256;
    const size_t O3T = 8UL * 96 * 256;

    // ================= Stage 1 pre on s0 (saturating) =================
    conv_s2_lrelu<<<dim3(80 * 2, 4, 4), blk, 0, s0>>>(x, W1, b1, feat1,
                                                      1, 16, 128, 128, 16384, 163840);
    conv_pre<<<dim3(80 * 16, 4, 4), blk, 0, s0>>>(feat1, Wg1, bg1, gxg1, 16, 80, 128, 64, 64);
    conv_pre<<<dim3(80 * 8, 4, 4), blk, 0, s0>>>(feat1, Wc1, bc1, gxc1, 16, 80, 64, 64, 64);
    gru_t0<<<(8 * 64 * 4096 + 255) / 256, 256, 0, s0>>>(gxg1, gxc1, outs1, 64, 4096,
                                                        8 * 64 * 4096);
    cudaEventRecord(g_evT0, s0);

    // ===== Stage 1 recurrence: 8 independent per-batch chains =====
    for (int b = 0; b < 8; b++) {
        cudaStreamWaitEvent(g_s1[b], g_evT0, 0);
        for (int t = 1; t < 10; t++) {
            const float* hp = outs1 + (size_t)(t - 1) * O1T + (size_t)b * H1B;
            float* hn       = outs1 + (size_t)t * O1T + (size_t)b * H1B;
            const float* pg = gxg1 + (size_t)t * 8 * G1B + (size_t)b * G1B;
            const float* pc = gxc1 + (size_t)t * O1T + (size_t)b * H1B;
            float* gb       = gates1 + (size_t)b * G1B;
            gru_conv_h<<<dim3(16, 4, 4), blk, 0, g_s1[b]>>>(hp, Wg1, pg, gb, gb,
                                                            16, 80, 64, 128, 64, 64, 0);
            gru_conv_h<<<dim3(8, 4, 4), blk, 0, g_s1[b]>>>(hp, Wc1, pc, gb, hn,
                                                           16, 80, 64, 64, 64, 64, 1);
            cudaEventRecord(g_e1[b][t], g_s1[b]);
        }
    }

    // ================= Stage 2 pre (stream B) =================
    for (int t = 0; t < 10; t++) {
        if (t == 0) cudaStreamWaitEvent(g_sB, g_evT0, 0);
        else for (int b = 0; b < 8; b++) cudaStreamWaitEvent(g_sB, g_e1[b][t], 0);
        conv_s2_lrelu<<<dim3(8 * 8, 2, 2), blk, 0, g_sB>>>(outs1 + (size_t)t * O1T, W2, b2,
                                                           feat2 + (size_t)t * F2T,
                                                           64, 64, 64, 64, 0, 64 * 4096);
        conv_pre<<<dim3(8 * 24, 2, 2), blk, 0, g_sB>>>(feat2 + (size_t)t * F2T, Wg2, bg2,
                                                       gxg2 + (size_t)t * GG2,
                                                       64, 160, 192, 32, 32);
        conv_pre<<<dim3(8 * 12, 2, 2), blk, 0, g_sB>>>(feat2 + (size_t)t * F2T, Wc2, bc2,
                                                       gxc2 + (size_t)t * GC2,
                                                       64, 160, 96, 32, 32);
        cudaEventRecord(g_evB[t], g_sB);
    }

    // ================= Stage 2 recurrence (stream C) =================
    cudaStreamWaitEvent(g_sC, g_evB[0], 0);
    gru_t0<<<(int)((O2T + 255) / 256), 256, 0, g_sC>>>(gxg2, gxc2, outs2, 96, 1024, (int)O2T);
    cudaEventRecord(g_ev2[0], g_sC);
    for (int t = 1; t < 10; t++) {
        cudaStreamWaitEvent(g_sC, g_evB[t], 0);
        const float* hp = outs2 + (size_t)(t - 1) * O2T;
        float* hn = outs2 + (size_t)t * O2T;
        gru_conv_h<<<dim3(8 * 24, 2, 2), blk, 0, g_sC>>>(hp, Wg2, gxg2 + (size_t)t * GG2,
                                                         gates2, gates2, 64, 160, 96, 192, 32, 32, 0);
        gru_conv_h<<<dim3(8 * 12, 2, 2), blk, 0, g_sC>>>(hp, Wc2, gxc2 + (size_t)t * GC2,
                                                         gates2, hn, 64, 160, 96, 96, 32, 32, 1);
        cudaEventRecord(g_ev2[t], g_sC);
    }

    // ================= Stage 3 pre (stream D) =================
    for (int t = 0; t < 10; t++) {
        cudaStreamWaitEvent(g_sD, g_ev2[t], 0);
        conv_s2_lrelu<<<dim3(8 * 12, 1, 1), blk, 0, g_sD>>>(outs2 + (size_t)t * O2T, W3, b3,
                                                            feat3 + (size_t)t * F3T,
                                                            96, 96, 32, 32, 0, 96 * 1024);
        conv_pre<<<dim3(8 * 24, 1, 1), blk, 0, g_sD>>>(feat3 + (size_t)t * F3T, Wg3, bg3,
                                                       gxg3 + (size_t)t * GG3,
                                                       96, 192, 192, 16, 16);
        conv_pre<<<dim3(8 * 12, 1, 1), blk, 0, g_sD>>>(feat3 + (size_t)t * F3T, Wc3, bc3,
                                                       gxc3 + (size_t)t * GC3,
                                                       96, 192, 96, 16, 16);
        cudaEventRecord(g_evD[t], g_sD);
    }

    // ================= Stage 3 recurrence (stream E) =================
    cudaStreamWaitEvent(g_sE, g_evD[0], 0);
    gru_t0<<<(int)((O3T + 255) / 256), 256, 0, g_sE>>>(gxg3, gxc3, outs3, 96, 256, (int)O3T);
    for (int t = 1; t < 10; t++) {
        cudaStreamWaitEvent(g_sE, g_evD[t], 0);
        const float* hp = outs3 + (size_t)(t - 1) * O3T;
        float* hn = outs3 + (size_t)t * O3T;
        gru_conv_h<<<dim3(8 * 24, 1, 1), blk, 0, g_sE>>>(hp, Wg3, gxg3 + (size_t)t * GG3,
                                                         gates3, gates3, 96, 192, 96, 192, 16, 16, 0);
        gru_conv_h<<<dim3(8 * 12, 1, 1), blk, 0, g_sE>>>(hp, Wc3, gxc3 + (size_t)t * GC3,
                                                         gates3, hn, 96, 192, 96, 96, 16, 16, 1);
    }
    cudaEventRecord(g_evE, g_sE);

    // ---------------- Join all forked streams back into s0 ----------------
    cudaStreamWaitEvent(s0, g_evB[9], 0);
    cudaStreamWaitEvent(s0, g_ev2[9], 0);
    cudaStreamWaitEvent(s0, g_evD[9], 0);
    cudaStreamWaitEvent(s0, g_evE, 0);

    // ---------------- Assemble output: (h1, h2, h3) flattened ----------------
    float* out = (float*)d_out;
    cudaMemcpyAsync(out, outs1 + 9UL * O1T,
                    O1T * sizeof(float), cudaMemcpyDeviceToDevice, s0);
    cudaMemcpyAsync(out + 2097152, outs2 + 9UL * O2T,
                    O2T * sizeof(float), cudaMemcpyDeviceToDevice, s0);
    cudaMemcpyAsync(out + 2097152 + 786432, outs3 + 9UL * O3T,
                    O3T * sizeof(float), cudaMemcpyDeviceToDevice, s0);
}

// round 17
// speedup vs baseline: 1.0098x; 1.0059x over previous
#include <cuda_runtime.h>
#include <math.h>

#define TS 16
#define CSTEP 8
#define CSTEP2 4

// Scratch (fp32): feat/outs/gates + hoisted x-part conv results
__device__ float g_scratch[141819904];

__device__ __forceinline__ float sigf(float x) { return 1.f / (1.f + __expf(-x)); }
__device__ __forceinline__ float ftanh(float x) {
    float e = __expf(2.f * x);
    return 1.f - 2.f / (e + 1.f);
}

// ---------------------------------------------------------------------------
// Tile loader: 8 channel planes of 18x19 (halo, zero-pad), strided by 128
// threads with incremental index arithmetic. withR: multiply by r-gate plane.
// ---------------------------------------------------------------------------
__device__ __forceinline__ void load_tile8(float* __restrict__ dst,
                                           const float* __restrict__ src,
                                           const float* __restrict__ rs,
                                           int oy0, int ox0, int H, int W, int HW,
                                           int tid, bool withR)
{
    int iy = tid / 18, ix = tid % 18;
    int gy = oy0 - 1 + iy, gx = ox0 - 1 + ix;
    int sof = iy * 19 + ix;
    int goff = gy * W + gx;
    if (withR) {
        for (int i = tid; i < CSTEP * 324; i += 128) {
            float v = 0.f;
            if ((unsigned)gy < (unsigned)H && (unsigned)gx < (unsigned)W)
                v = src[goff] * rs[goff];
            dst[sof] = v;
            ix += 2; iy += 7; gy += 7; gx += 2;
            goff += 7 * W + 2; sof += 135;
            if (ix >= 18) { ix -= 18; gx -= 18; iy += 1; gy += 1;
                            goff += W - 18; sof += 1; }
            if (iy >= 18) { iy -= 18; gy -= 18; goff += HW - 18 * W; }
        }
    } else {
        for (int i = tid; i < CSTEP * 324; i += 128) {
            float v = 0.f;
            if ((unsigned)gy < (unsigned)H && (unsigned)gx < (unsigned)W)
                v = src[goff];
            dst[sof] = v;
            ix += 2; iy += 7; gy += 7; gx += 2;
            goff += 7 * W + 2; sof += 135;
            if (ix >= 18) { ix -= 18; gx -= 18; iy += 1; gy += 1;
                            goff += W - 18; sof += 1; }
            if (iy >= 18) { iy -= 18; gy -= 18; goff += HW - 18 * W; }
        }
    }
}

// weights loader: 8c x 8co x 9 into flattened [8][8][12]
__device__ __forceinline__ void load_ws8(float* __restrict__ wdst,
                                         const float* __restrict__ Wt,
                                         int co0, int CinTot, int woff, int ci0,
                                         int tid)
{
    for (int i = tid; i < CSTEP * 72; i += 128) {
        int c = i / 72, r = i % 72;
        int co = r / 9, kk = r % 9;
        wdst[c * 96 + co * 12 + kk] =
            Wt[((size_t)(co0 + co) * CinTot + woff + ci0 + c) * 9 + kk];
    }
}

// compute one 8-channel chunk from smem buffers (unchanged math/order)
__device__ __forceinline__ void compute_chunk(const float (* __restrict__ tile)[18][19],
                                              const float (* __restrict__ ws)[8][12],
                                              int tx, int ty,
                                              float acc0[8], float acc1[8])
{
#pragma unroll
    for (int c = 0; c < CSTEP; c++) {
        float a[4][3];
#pragma unroll
        for (int i = 0; i < 4; i++)
#pragma unroll
            for (int j = 0; j < 3; j++)
                a[i][j] = tile[c][2 * ty + i][tx + j];
#pragma unroll
        for (int co = 0; co < 8; co++) {
            float4 wa = *(const float4*)&ws[c][co][0];
            float4 wb = *(const float4*)&ws[c][co][4];
            float w8  = ws[c][co][8];
            acc0[co] += a[0][0]*wa.x + a[0][1]*wa.y + a[0][2]*wa.z
                      + a[1][0]*wa.w + a[1][1]*wb.x + a[1][2]*wb.y
                      + a[2][0]*wb.z + a[2][1]*wb.w + a[2][2]*w8;
            acc1[co] += a[1][0]*wa.x + a[1][1]*wa.y + a[1][2]*wa.z
                      + a[2][0]*wa.w + a[2][1]*wb.x + a[2][2]*wb.y
                      + a[3][0]*wb.z + a[3][1]*wb.w + a[3][2]*w8;
        }
    }
}

// ---------------------------------------------------------------------------
// Batched stride-1 3x3 conv (pad 1), double-buffered smem pipeline.
// grid: (N * Cout/8, H/16, W/16), block (16,8)
// ---------------------------------------------------------------------------
__global__ __launch_bounds__(128)
void conv_pre(const float* __restrict__ in, const float* __restrict__ Wt,
              const float* __restrict__ bias, float* __restrict__ out,
              int Cin, int CinTot, int Cout, int H, int W)
{
    int coutBlocks = Cout >> 3;
    int n   = blockIdx.x / coutBlocks;
    int co0 = (blockIdx.x % coutBlocks) * 8;
    int oy0 = blockIdx.y * TS;
    int ox0 = blockIdx.z * TS;
    int tx = threadIdx.x, ty = threadIdx.y;
    int tid = ty * 16 + tx;

    __shared__ float tile[2][CSTEP][18][19];
    __shared__ __align__(16) float ws[2][CSTEP][8][12];

    int HW = H * W;
    const float* inN = in + (size_t)n * Cin * HW;

    float acc0[8], acc1[8];
#pragma unroll
    for (int i = 0; i < 8; i++) { acc0[i] = 0.f; acc1[i] = 0.f; }

    load_tile8(&tile[0][0][0][0], inN, nullptr, oy0, ox0, H, W, HW, tid, false);
    load_ws8(&ws[0][0][0][0], Wt, co0, CinTot, 0, 0, tid);

    int cur = 0;
    for (int ci0 = 0; ci0 < Cin; ci0 += CSTEP) {
        __syncthreads();
        int nxt = ci0 + CSTEP;
        if (nxt < Cin) {
            load_tile8(&tile[cur ^ 1][0][0][0], inN + (size_t)nxt * HW, nullptr,
                       oy0, ox0, H, W, HW, tid, false);
            load_ws8(&ws[cur ^ 1][0][0][0], Wt, co0, CinTot, 0, nxt, tid);
        }
        compute_chunk(tile[cur], ws[cur], tx, ty, acc0, acc1);
        cur ^= 1;
    }

    int oy = oy0 + 2 * ty, ox = ox0 + tx;
#pragma unroll
    for (int co = 0; co < 8; co++) {
        float bz = bias[co0 + co];
        size_t o = ((size_t)n * Cout + co0 + co) * HW + (size_t)oy * W + ox;
        out[o]     = acc0[co] + bz;
        out[o + W] = acc1[co] + bz;
    }
}

// ---------------------------------------------------------------------------
// Recurrent h-part conv (t >= 1), double-buffered. mode 0: gates -> sigmoid.
// mode 1: cand (r*h in loader) -> GRU update. Seeded by pre (= bias + x-part).
// grid: (B * Cout/8, H/16, W/16)
// ---------------------------------------------------------------------------
__global__ __launch_bounds__(128)
void gru_conv_h(const float* __restrict__ hprev, const float* __restrict__ Wt,
                const float* __restrict__ pre, const float* __restrict__ gatesIn,
                float* __restrict__ out,
                int Cx, int CinTot, int Ch, int Cout, int H, int W, int mode)
{
    int coutBlocks = Cout >> 3;
    int b   = blockIdx.x / coutBlocks;
    int co0 = (blockIdx.x % coutBlocks) * 8;
    int oy0 = blockIdx.y * TS;
    int ox0 = blockIdx.z * TS;
    int tx = threadIdx.x, ty = threadIdx.y;
    int tid = ty * 16 + tx;

    __shared__ float tile[2][CSTEP][18][19];
    __shared__ __align__(16) float ws[2][CSTEP][8][12];

    int HW = H * W;
    const float* hbase = hprev + (size_t)b * Ch * HW;
    const float* rbase = gatesIn + (size_t)b * 2 * Ch * HW;
    bool withR = (mode != 0);

    float acc0[8], acc1[8];
#pragma unroll
    for (int i = 0; i < 8; i++) { acc0[i] = 0.f; acc1[i] = 0.f; }

    load_tile8(&tile[0][0][0][0], hbase, rbase, oy0, ox0, H, W, HW, tid, withR);
    load_ws8(&ws[0][0][0][0], Wt, co0, CinTot, Cx, 0, tid);

    int cur = 0;
    for (int ci0 = 0; ci0 < Ch; ci0 += CSTEP) {
        __syncthreads();
        int nxt = ci0 + CSTEP;
        if (nxt < Ch) {
            load_tile8(&tile[cur ^ 1][0][0][0], hbase + (size_t)nxt * HW,
                       rbase + (size_t)nxt * HW, oy0, ox0, H, W, HW, tid, withR);
            load_ws8(&ws[cur ^ 1][0][0][0], Wt, co0, CinTot, Cx, nxt, tid);
        }
        compute_chunk(tile[cur], ws[cur], tx, ty, acc0, acc1);
        cur ^= 1;
    }

    int oy = oy0 + 2 * ty, ox = ox0 + tx;
    if (mode == 0) {
#pragma unroll
        for (int co = 0; co < 8; co++) {
            size_t po = ((size_t)b * Cout + co0 + co) * HW + (size_t)oy * W + ox;
            float p0 = pre[po], p1 = pre[po + W];
            size_t o = (((size_t)b * Cout + co0 + co) * H + oy) * W + ox;
            out[o]     = sigf(acc0[co] + p0);
            out[o + W] = sigf(acc1[co] + p1);
        }
    } else {
#pragma unroll
        for (int co = 0; co < 8; co++) {
            int cc = co0 + co;
            size_t po = ((size_t)b * Cout + cc) * HW + (size_t)oy * W + ox;
            float p0 = pre[po], p1 = pre[po + W];
            size_t zo = (((size_t)b * 2 * Ch + Ch + cc) * H + oy) * W + ox;
            float z0 = gatesIn[zo], z1 = gatesIn[zo + W];
            size_t ho = (((size_t)b * Ch + cc) * H + oy) * W + ox;
            float h0v = hprev[ho], h1v = hprev[ho + W];
            out[ho]     = z0 * h0v + (1.f - z0) * ftanh(acc0[co] + p0);
            out[ho + W] = z1 * h1v + (1.f - z1) * ftanh(acc1[co] + p1);
        }
    }
}

// ---------------------------------------------------------------------------
// t = 0 step (h == 0): hn = (1 - sigmoid(z_pre)) * tanh(c_pre), elementwise.
// ---------------------------------------------------------------------------
__global__ void gru_t0(const float* __restrict__ gz, const float* __restrict__ gc,
                       float* __restrict__ hn, int Ch, int HW, int total)
{
    int i = blockIdx.x * 256 + threadIdx.x;
    if (i >= total) return;
    int b = i / (Ch * HW);
    float z = sigf(gz[(size_t)i + (size_t)(b + 1) * Ch * HW]);
    hn[i] = (1.f - z) * ftanh(gc[i]);
}

// ---------------------------------------------------------------------------
// Stride-2 3x3 conv (pad 1) + leaky relu(0.2).
// ---------------------------------------------------------------------------
__global__ void conv_s2_lrelu(const float* __restrict__ in, const float* __restrict__ Wt,
                              const float* __restrict__ bias, float* __restrict__ out,
                              int Cin, int Cout, int Hin, int Win, int sOuter, int sInner)
{
    int coutBlocks = Cout >> 3;
    int n  = blockIdx.x / coutBlocks;
    int cb = blockIdx.x % coutBlocks;
    int co0 = cb * 8;
    int t = n / 8, b = n % 8;
    const float* inN = in + (size_t)t * sOuter + (size_t)b * sInner;
    int Hout = Hin >> 1, Wout = Win >> 1;
    int oy0 = blockIdx.y * TS, ox0 = blockIdx.z * TS;
    int tx = threadIdx.x, ty = threadIdx.y;
    int tid = ty * 16 + tx;

    __shared__ float tile[CSTEP2][33][35];
    __shared__ float ws[CSTEP2][8][9];

    float acc0[8], acc1[8];
#pragma unroll
    for (int i = 0; i < 8; i++) { acc0[i] = 0.f; acc1[i] = 0.f; }

    for (int ci0 = 0; ci0 < Cin; ci0 += CSTEP2) {
        __syncthreads();
        for (int i = tid; i < CSTEP2 * 1089; i += 128) {
            int c = i / 1089, p = i % 1089;
            int ly = p / 33, lx = p % 33;
            int gy = 2 * oy0 - 1 + ly, gx = 2 * ox0 - 1 + lx;
            float v = 0.f;
            int ci = ci0 + c;
            if (ci < Cin && gy >= 0 && gy < Hin && gx >= 0 && gx < Win)
                v = inN[((size_t)ci * Hin + gy) * Win + gx];
            tile[c][ly][lx] = v;
        }
        for (int i = tid; i < CSTEP2 * 72; i += 128) {
            int c = i / 72, r = i % 72;
            int co = r / 9, k = r % 9;
            float wv = 0.f;
            if (ci0 + c < Cin)
                wv = Wt[((size_t)(co0 + co) * Cin + (ci0 + c)) * 9 + k];
            ws[c][co][k] = wv;
        }
        __syncthreads();

#pragma unroll
        for (int c = 0; c < CSTEP2; c++) {
            float a[5][3];
#pragma unroll
            for (int i = 0; i < 5; i++)
#pragma unroll
                for (int j = 0; j < 3; j++)
                    a[i][j] = tile[c][4 * ty + i][2 * tx + j];
#pragma unroll
            for (int co = 0; co < 8; co++) {
                float w0 = ws[c][co][0], w1 = ws[c][co][1], w2 = ws[c][co][2];
                float w3 = ws[c][co][3], w4 = ws[c][co][4], w5 = ws[c][co][5];
                float w6 = ws[c][co][6], w7 = ws[c][co][7], w8 = ws[c][co][8];
                acc0[co] += a[0][0]*w0 + a[0][1]*w1 + a[0][2]*w2
                          + a[1][0]*w3 + a[1][1]*w4 + a[1][2]*w5
                          + a[2][0]*w6 + a[2][1]*w7 + a[2][2]*w8;
                acc1[co] += a[2][0]*w0 + a[2][1]*w1 + a[2][2]*w2
                          + a[3][0]*w3 + a[3][1]*w4 + a[3][2]*w5
                          + a[4][0]*w6 + a[4][1]*w7 + a[4][2]*w8;
            }
        }
    }

    int oy = oy0 + 2 * ty, ox = ox0 + tx;
#pragma unroll
    for (int co = 0; co < 8; co++) {
        float bz = bias[co0 + co];
        float v0 = acc0[co] + bz, v1 = acc1[co] + bz;
        v0 = v0 > 0.f ? v0 : 0.2f * v0;
        v1 = v1 > 0.f ? v1 : 0.2f * v1;
        size_t o = (((size_t)n * Cout + co0 + co) * Hout + oy) * Wout + ox;
        out[o]        = v0;
        out[o + Wout] = v1;
    }
}

// ---------------- streams/events (created once at load time) ----------------
static cudaStream_t g_sB, g_sC, g_sD, g_sE, g_sF;
static cudaEvent_t g_ev1[10], g_evB[10], g_ev2[10], g_evD[10], g_evE, g_evS2, g_evP[10];
static bool g_streams_ok = [] {
    cudaStreamCreateWithFlags(&g_sB, cudaStreamNonBlocking);
    cudaStreamCreateWithFlags(&g_sC, cudaStreamNonBlocking);
    cudaStreamCreateWithFlags(&g_sD, cudaStreamNonBlocking);
    cudaStreamCreateWithFlags(&g_sE, cudaStreamNonBlocking);
    cudaStreamCreateWithFlags(&g_sF, cudaStreamNonBlocking);
    for (int i = 0; i < 10; i++) {
        cudaEventCreateWithFlags(&g_ev1[i], cudaEventDisableTiming);
        cudaEventCreateWithFlags(&g_evB[i], cudaEventDisableTiming);
        cudaEventCreateWithFlags(&g_ev2[i], cudaEventDisableTiming);
        cudaEventCreateWithFlags(&g_evD[i], cudaEventDisableTiming);
        cudaEventCreateWithFlags(&g_evP[i], cudaEventDisableTiming);
    }
    cudaEventCreateWithFlags(&g_evE, cudaEventDisableTiming);
    cudaEventCreateWithFlags(&g_evS2, cudaEventDisableTiming);
    return true;
}();

extern "C" void kernel_launch(void* const* d_in, const int* in_sizes, int n_in,
                              void* d_out, int out_size)
{
    const float* x   = (const float*)d_in[0];
    const float* W1  = (const float*)d_in[1];
    const float* b1  = (const float*)d_in[2];
    const float* Wg1 = (const float*)d_in[3];
    const float* bg1 = (const float*)d_in[4];
    const float* Wc1 = (const float*)d_in[5];
    const float* bc1 = (const float*)d_in[6];
    const float* W2  = (const float*)d_in[7];
    const float* b2  = (const float*)d_in[8];
    const float* Wg2 = (const float*)d_in[9];
    const float* bg2 = (const float*)d_in[10];
    const float* Wc2 = (const float*)d_in[11];
    const float* bc2 = (const float*)d_in[12];
    const float* W3  = (const float*)d_in[13];
    const float* b3  = (const float*)d_in[14];
    const float* Wg3 = (const float*)d_in[15];
    const float* bg3 = (const float*)d_in[16];
    const float* Wc3 = (const float*)d_in[17];
    const float* bc3 = (const float*)d_in[18];

    float* base = nullptr;
    cudaGetSymbolAddress((void**)&base, g_scratch);

    float* feat1  = base;                   // 5,242,880
    float* outs1  = base + 5242880;         // 20,971,520
    float* feat2  = base + 26214400;        // 5,242,880
    float* outs2  = base + 31457280;        // 7,864,320
    float* feat3  = base + 39321600;        // 1,966,080
    float* outs3  = base + 41287680;        // 1,966,080
    float* gates1 = base + 43253760;        // 4,194,304 (8*128*4096)
    float* gxg1   = base + 47448064;        // 41,943,040
    float* gxc1   = base + 89391104;        // 20,971,520
    float* gxg2   = base + 110362624;       // 15,728,640
    float* gxc2   = base + 126091264;       // 7,864,320
    float* gxg3   = base + 133955584;       // 3,932,160
    float* gxc3   = base + 137887744;       // 1,966,080
    float* gates2 = base + 139853824;       // 1,572,864 (8*192*1024)
    float* gates3 = base + 141426688;       // 393,216   (8*192*256)

    dim3 blk(16, 8);
    cudaStream_t s0 = 0;

    const size_t O1T = 8UL * 64 * 4096;   // outs1 per t
    const size_t F1T = 8UL * 16 * 4096;   // feat1 per t
    const size_t GG1 = 8UL * 128 * 4096;  // gxg1 per t
    const size_t F2T = 8UL * 64 * 1024;
    const size_t GG2 = 8UL * 192 * 1024;
    const size_t GC2 = 8UL * 96 * 1024;
    const size_t O2T = 8UL * 96 * 1024;
    const size_t F3T = 8UL * 96 * 256;
    const size_t GG3 = 8UL * 192 * 256;
    const size_t GC3 = 8UL * 96 * 256;
    const size_t O3T = 8UL * 96 * 256;

    // ================= Stage 1: s2 conv, then t=0 pre + t0 step on s0 =========
    conv_s2_lrelu<<<dim3(80 * 2, 4, 4), blk, 0, s0>>>(x, W1, b1, feat1,
                                                      1, 16, 128, 128, 16384, 163840);
    cudaEventRecord(g_evS2, s0);
    conv_pre<<<dim3(8 * 16, 4, 4), blk, 0, s0>>>(feat1, Wg1, bg1, gxg1, 16, 80, 128, 64, 64);
    conv_pre<<<dim3(8 * 8, 4, 4), blk, 0, s0>>>(feat1, Wc1, bc1, gxc1, 16, 80, 64, 64, 64);
    gru_t0<<<(8 * 64 * 4096 + 255) / 256, 256, 0, s0>>>(gxg1, gxc1, outs1, 64, 4096,
                                                        8 * 64 * 4096);
    cudaEventRecord(g_ev1[0], s0);

    // ===== Stage 1 pre for t=1..9 on stream F (fills early recurrence gaps) ===
    for (int t = 1; t < 10; t++) {
        if (t == 1) cudaStreamWaitEvent(g_sF, g_evS2, 0);
        conv_pre<<<dim3(8 * 16, 4, 4), blk, 0, g_sF>>>(feat1 + (size_t)t * F1T, Wg1, bg1,
                                                       gxg1 + (size_t)t * GG1,
                                                       16, 80, 128, 64, 64);
        conv_pre<<<dim3(8 * 8, 4, 4), blk, 0, g_sF>>>(feat1 + (size_t)t * F1T, Wc1, bc1,
                                                      gxc1 + (size_t)t * O1T,
                                                      16, 80, 64, 64, 64);
        cudaEventRecord(g_evP[t], g_sF);
    }

    // ===== Stage 1 recurrence on s0 =====
    for (int t = 1; t < 10; t++) {
        cudaStreamWaitEvent(s0, g_evP[t], 0);
        const float* hp = outs1 + (size_t)(t - 1) * O1T;
        float* hn = outs1 + (size_t)t * O1T;
        gru_conv_h<<<dim3(8 * 16, 4, 4), blk, 0, s0>>>(hp, Wg1, gxg1 + (size_t)t * GG1,
                                                       gates1, gates1, 16, 80, 64, 128, 64, 64, 0);
        gru_conv_h<<<dim3(8 * 8, 4, 4), blk, 0, s0>>>(hp, Wc1, gxc1 + (size_t)t * O1T,
                                                      gates1, hn, 16, 80, 64, 64, 64, 64, 1);
        cudaEventRecord(g_ev1[t], s0);
    }

    // ================= Stage 2 pre (stream B) =================
    for (int t = 0; t < 10; t++) {
        cudaStreamWaitEvent(g_sB, g_ev1[t], 0);
        conv_s2_lrelu<<<dim3(8 * 8, 2, 2), blk, 0, g_sB>>>(outs1 + (size_t)t * O1T, W2, b2,
                                                           feat2 + (size_t)t * F2T,
                                                           64, 64, 64, 64, 0, 64 * 4096);
        conv_pre<<<dim3(8 * 24, 2, 2), blk, 0, g_sB>>>(feat2 + (size_t)t * F2T, Wg2, bg2,
                                                       gxg2 + (size_t)t * GG2,
                                                       64, 160, 192, 32, 32);
        conv_pre<<<dim3(8 * 12, 2, 2), blk, 0, g_sB>>>(feat2 + (size_t)t * F2T, Wc2, bc2,
                                                       gxc2 + (size_t)t * GC2,
                                                       64, 160, 96, 32, 32);
        cudaEventRecord(g_evB[t], g_sB);
    }

    // ================= Stage 2 recurrence (stream C) =================
    cudaStreamWaitEvent(g_sC, g_evB[0], 0);
    gru_t0<<<(int)((O2T + 255) / 256), 256, 0, g_sC>>>(gxg2, gxc2, outs2, 96, 1024, (int)O2T);
    cudaEventRecord(g_ev2[0], g_sC);
    for (int t = 1; t < 10; t++) {
        cudaStreamWaitEvent(g_sC, g_evB[t], 0);
        const float* hp = outs2 + (size_t)(t - 1) * O2T;
        float* hn = outs2 + (size_t)t * O2T;
        gru_conv_h<<<dim3(8 * 24, 2, 2), blk, 0, g_sC>>>(hp, Wg2, gxg2 + (size_t)t * GG2,
                                                         gates2, gates2, 64, 160, 96, 192, 32, 32, 0);
        gru_conv_h<<<dim3(8 * 12, 2, 2), blk, 0, g_sC>>>(hp, Wc2, gxc2 + (size_t)t * GC2,
                                                         gates2, hn, 64, 160, 96, 96, 32, 32, 1);
        cudaEventRecord(g_ev2[t], g_sC);
    }

    // ================= Stage 3 pre (stream D) =================
    for (int t = 0; t < 10; t++) {
        cudaStreamWaitEvent(g_sD, g_ev2[t], 0);
        conv_s2_lrelu<<<dim3(8 * 12, 1, 1), blk, 0, g_sD>>>(outs2 + (size_t)t * O2T, W3, b3,
                                                            feat3 + (size_t)t * F3T,
                                                            96, 96, 32, 32, 0, 96 * 1024);
        conv_pre<<<dim3(8 * 24, 1, 1), blk, 0, g_sD>>>(feat3 + (size_t)t * F3T, Wg3, bg3,
                                                       gxg3 + (size_t)t * GG3,
                                                       96, 192, 192, 16, 16);
        conv_pre<<<dim3(8 * 12, 1, 1), blk, 0, g_sD>>>(feat3 + (size_t)t * F3T, Wc3, bc3,
                                                       gxc3 + (size_t)t * GC3,
                                                       96, 192, 96, 16, 16);
        cudaEventRecord(g_evD[t], g_sD);
    }

    // ================= Stage 3 recurrence (stream E) =================
    cudaStreamWaitEvent(g_sE, g_evD[0], 0);
    gru_t0<<<(int)((O3T + 255) / 256), 256, 0, g_sE>>>(gxg3, gxc3, outs3, 96, 256, (int)O3T);
    for (int t = 1; t < 10; t++) {
        cudaStreamWaitEvent(g_sE, g_evD[t], 0);
        const float* hp = outs3 + (size_t)(t - 1) * O3T;
        float* hn = outs3 + (size_t)t * O3T;
        gru_conv_h<<<dim3(8 * 24, 1, 1), blk, 0, g_sE>>>(hp, Wg3, gxg3 + (size_t)t * GG3,
                                                         gates3, gates3, 96, 192, 96, 192, 16, 16, 0);
        gru_conv_h<<<dim3(8 * 12, 1, 1), blk, 0, g_sE>>>(hp, Wc3, gxc3 + (size_t)t * GC3,
                                                         gates3, hn, 96, 192, 96, 96, 16, 16, 1);
    }
    cudaEventRecord(g_evE, g_sE);

    // ---------------- Join all forked streams back into s0 ----------------
    cudaStreamWaitEvent(s0, g_evB[9], 0);
    cudaStreamWaitEvent(s0, g_ev2[9], 0);
    cudaStreamWaitEvent(s0, g_evD[9], 0);
    cudaStreamWaitEvent(s0, g_evE, 0);
    cudaStreamWaitEvent(s0, g_evP[9], 0);

    // ---------------- Assemble output: (h1, h2, h3) flattened ----------------
    float* out = (float*)d_out;
    cudaMemcpyAsync(out, outs1 + 9UL * O1T,
                    O1T * sizeof(float), cudaMemcpyDeviceToDevice, s0);
    cudaMemcpyAsync(out + 2097152, outs2 + 9UL * O2T,
                    O2T * sizeof(float), cudaMemcpyDeviceToDevice, s0);
    cudaMemcpyAsync(out + 2097152 + 786432, outs3 + 9UL * O3T,
                    O3T * sizeof(float), cudaMemcpyDeviceToDevice, s0);
}